// round 16
// baseline (speedup 1.0000x reference)
#include <cuda_runtime.h>
#include <math.h>

// Problem: B=64, T=512, V=50000, E=300, H1=256, H2=512, D1=128, D2=64, C=1
// Inputs: tokens, emb, W1x, W1h, b1, W2x, W2h, b2, Wd1, bd1, Wd2, bd2, Wc, bc

typedef unsigned long long ull;

// ---------------- packed f32x2 helpers ----------------
__device__ __forceinline__ ull pack2(float lo, float hi) {
    ull r; asm("mov.b64 %0,{%1,%2};" : "=l"(r) : "f"(lo), "f"(hi)); return r;
}
__device__ __forceinline__ ull splat2(float v) { return pack2(v, v); }
__device__ __forceinline__ float2 unpack2(ull v) {
    float2 r; asm("mov.b64 {%0,%1},%2;" : "=f"(r.x), "=f"(r.y) : "l"(v)); return r;
}
__device__ __forceinline__ ull fma2(ull a, ull b, ull c) {
    ull d; asm("fma.rn.f32x2 %0,%1,%2,%3;" : "=l"(d) : "l"(a), "l"(b), "l"(c)); return d;
}
__device__ __forceinline__ ull add2(ull a, ull b) {
    ull d; asm("add.rn.f32x2 %0,%1,%2;" : "=l"(d) : "l"(a), "l"(b)); return d;
}
// ---------------- L2 flag sync (no cluster, no sleep) ----------------
__device__ __forceinline__ void fence_gpu_() {
    asm volatile("fence.acq_rel.gpu;" ::: "memory");
}
__device__ __forceinline__ void flag_add1(unsigned* p) {
    asm volatile("red.relaxed.gpu.global.add.u32 [%0], 1;" :: "l"(p) : "memory");
}
__device__ __forceinline__ unsigned flag_ld(const unsigned* p) {
    unsigned v;
    asm volatile("ld.acquire.gpu.global.u32 %0, [%1];" : "=r"(v) : "l"(p) : "memory");
    return v;
}

// ---------------- static device scratch ----------------
__device__ float g_xw1[(size_t)64 * 512 * 256];       // xw1[b][t][j]
__device__ float g_h1T[4][2][2][256][8];              // [cl][g][buf][k][b]
__device__ float g_h2T[4][2][2][512][8];
__device__ float g_h2[64 * 512];                      // final h2(511) for the head
__device__ __align__(128) unsigned g_flag[4][2][32];  // [cl][g][line]

// =====================================================================
// Kernel 1: xw1[b,t,:] = emb[tokens[b,t]] @ W1x + b1  (+ flag reset)
// =====================================================================
__global__ void __launch_bounds__(256, 2)
embproj_kernel(const int* __restrict__ tokens, const float* __restrict__ emb,
               const float* __restrict__ W1x, const float* __restrict__ b1)
{
    __shared__ int    t_sm[32];
    __shared__ float4 a_sm[300 * 9];

    const int tid  = threadIdx.x;
    const int base = blockIdx.x * 32;

    // reset group sync counters for this launch (graph replays included)
    if (blockIdx.x == 0 && tid < 8) g_flag[tid >> 1][tid & 1][0] = 0u;

    if (tid < 32) t_sm[tid] = tokens[base + tid];
    __syncthreads();

    {
        const int m4 = tid >> 6;
        const int e0 = tid & 63;
        for (int mm = m4; mm < 8; mm += 4) {
            const int i0 = mm * 4;
            const size_t r0 = (size_t)t_sm[i0 + 0] * 300;
            const size_t r1 = (size_t)t_sm[i0 + 1] * 300;
            const size_t r2 = (size_t)t_sm[i0 + 2] * 300;
            const size_t r3 = (size_t)t_sm[i0 + 3] * 300;
            for (int e = e0; e < 300; e += 64) {
                float4 v;
                v.x = __ldg(emb + r0 + e);
                v.y = __ldg(emb + r1 + e);
                v.z = __ldg(emb + r2 + e);
                v.w = __ldg(emb + r3 + e);
                a_sm[e * 9 + mm] = v;
            }
        }
    }
    __syncthreads();

    const int j = tid;
    ull acc[16];
#pragma unroll
    for (int m = 0; m < 16; ++m) acc[m] = 0ull;

    const float* wp = W1x + j;
#pragma unroll 4
    for (int e = 0; e < 300; ++e) {
        const ull ws = splat2(__ldg(wp + (size_t)e * 256));
        const ulonglong2* ap = (const ulonglong2*)(a_sm + e * 9);
#pragma unroll
        for (int m2 = 0; m2 < 8; ++m2) {
            ulonglong2 s = ap[m2];
            acc[2 * m2]     = fma2(ws, s.x, acc[2 * m2]);
            acc[2 * m2 + 1] = fma2(ws, s.y, acc[2 * m2 + 1]);
        }
    }

    const float bj = __ldg(b1 + j);
#pragma unroll
    for (int m = 0; m < 16; ++m) {
        float2 v = unpack2(acc[m]);
        const size_t row = (size_t)(base + 2 * m);
        g_xw1[row * 256 + j]       = v.x + bj;
        g_xw1[(row + 1) * 256 + j] = v.y + bj;
    }
}

// =====================================================================
// nop kernels: keep ncu capture landing on rnn_kernel (launch idx 3)
// =====================================================================
__global__ void nop_kernel() {}
__global__ void nop_kernel2() {}

// =====================================================================
// Kernel 2: fused 2-layer recurrence (v13: 32-CTA groups, batch-pair h).
// 128 CTAs in 4 groups of 32. Group owns 16 batches as 2 pipelined
// sub-groups of 8 (g = n&1, t = n>>1, 1024 iterations). CTA r owns
// layer-2 cols [16r,+16), layer-1 cols [8r,+8): W2h slice = 32 KB/sub-iter.
// h stored UNSPLATTED as [k][8 batches] floats — ulonglong2 views are the
// batch pairs; weights are scalar + in-register splat2. Stage STS has no
// doubling (24 KB). Sync identical to R13/R15 (flag spin, mid-compute
// poll+prefetch on stager threads).
// =====================================================================
#define RNN_SMEM_BYTES (34816 + 49152 + 8192 + 4096 + 64)

__global__ void __launch_bounds__(512, 1)
rnn_kernel(const float* __restrict__ W1h, const float* __restrict__ W2x,
           const float* __restrict__ W2h, const float* __restrict__ b2)
{
    extern __shared__ float smem[];
    float* w2h_s = smem;                          // [512][17] 34816 B (padded)
    float* hd    = smem + 8704;                   // [2][768][8] 48 KB
    float* red2  = hd + 2 * 768 * 8;              // [16][16][8]  8 KB
    float* red1  = red2 + 2048;                   // [16][8][8]   4 KB
    float* b2_s  = red1 + 1024;                   // [16]

    const int tid  = threadIdx.x;
    const int rank = blockIdx.x & 31;
    const int cl   = blockIdx.x >> 5;              // 4 groups
    const int B0   = cl * 16;
    const int c1 = rank * 8, c2 = rank * 16;
    const int j2 = tid & 15, kg  = tid >> 4;       // layer-2: 32 kg x 16 cols
    const int j1 = tid & 7,  kg1 = tid >> 3;       // layer-1: 64 kg x 8 cols
    const int wid = tid >> 5;

    // ---- W2h slice -> SMEM (padded rows: 17 floats) ----
    for (int idx = tid; idx < 512 * 16; idx += 512) {
        const int k = idx >> 4, j = idx & 15;
        w2h_s[k * 17 + j] = W2h[(size_t)k * 512 + c2 + j];
    }
    // ---- W2x slice -> registers (8 scalars, k in [8kg, 8kg+8)) ----
    float w2x_r[8];
#pragma unroll
    for (int r = 0; r < 8; ++r)
        w2x_r[r] = __ldg(W2x + (size_t)(kg * 8 + r) * 512 + c2 + j2);
    // ---- W1h slice -> registers (4 scalars, k in [4kg1, 4kg1+4)) ----
    float w1_r[4];
#pragma unroll
    for (int r = 0; r < 4; ++r)
        w1_r[r] = __ldg(W1h + (size_t)(kg1 * 4 + r) * 256 + c1 + j1);
    if (tid < 16) b2_s[tid] = b2[c2 + tid];

    // ---- init hd[0], hd[1]: h1(g,0) = relu(xw1); h2(g,-1) = 0 ----
    for (int idx = tid; idx < 1536; idx += 512) {
        const int g = idx >= 768, k = idx - g * 768;
#pragma unroll
        for (int bi = 0; bi < 8; ++bi) {
            float v = 0.f;
            if (k < 256)
                v = fmaxf(g_xw1[(size_t)((B0 + 8 * g + bi) * 512) * 256 + k], 0.f);
            hd[(size_t)g * 6144 + k * 8 + bi] = v;
        }
    }
    __syncthreads();
    // flags start at 0 (reset by embproj); h(g,0) lives only in local SMEM.

    for (int n = 0; n < 1024; ++n) {
        const int g = n & 1, t = n >> 1;
        const int tn = (n + 1) >> 1;               // timestep of NEXT iteration
        const bool do_stage = (n >= 1) && (n < 1023);

        // xnext for layer-1 finish (threads 128..191)
        float xnext = 0.f;
        if (tid >= 128 && tid < 192 && t < 511) {
            const int ii = tid - 128, b = ii & 7, jj = ii >> 3;
            xnext = __ldcg(&g_xw1[((size_t)((B0 + 8 * g + b) * 512 + t + 1)) * 256 + c1 + jj]);
        }

        const float* hb = hd + (size_t)g * 6144;
        ull a0 = 0, a1 = 0, a2 = 0, a3 = 0;        // batch pairs {01,23,45,67}

        // ---- part 1: W2h.h2 (16 k per thread) ----
        {
            const float* wp = w2h_s + (kg * 16) * 17 + j2;
#pragma unroll
            for (int r = 0; r < 16; ++r) {
                const ull ws = splat2(wp[r * 17]);
                const ulonglong2* ph = (const ulonglong2*)(hb + (256 + kg * 16 + r) * 8);
                const ulonglong2 p0 = ph[0], p1 = ph[1];
                a0 = fma2(ws, p0.x, a0);
                a1 = fma2(ws, p0.y, a1);
                a2 = fma2(ws, p1.x, a2);
                a3 = fma2(ws, p1.y, a3);
            }
        }

        // ---- mid-compute: stagers poll (fast path) + prefetch next h ----
        float4 pl0 = {}, ph0 = {}, pl1 = {}, ph1 = {}, pl2 = {}, ph2 = {};
        if (do_stage && tid >= 256) {
            const unsigned target = 32u * (unsigned)tn;
            const unsigned* fp = &g_flag[cl][g ^ 1][0];
            while (flag_ld(fp) < target) { }
            const int s = tid - 256;               // k = s, s+256, s+512
            const int nb = tn & 1;
            pl0 = __ldcg((const float4*)&g_h1T[cl][g ^ 1][nb][s][0]);
            ph0 = __ldcg((const float4*)&g_h1T[cl][g ^ 1][nb][s][4]);
            pl1 = __ldcg((const float4*)&g_h2T[cl][g ^ 1][nb][s][0]);
            ph1 = __ldcg((const float4*)&g_h2T[cl][g ^ 1][nb][s][4]);
            pl2 = __ldcg((const float4*)&g_h2T[cl][g ^ 1][nb][s + 256][0]);
            ph2 = __ldcg((const float4*)&g_h2T[cl][g ^ 1][nb][s + 256][4]);
        }

        // ---- part 2: W2x.h1 (8 k) + shfl-combine -> red2 ----
        {
#pragma unroll
            for (int r = 0; r < 8; ++r) {
                const ull ws = splat2(w2x_r[r]);
                const ulonglong2* ph = (const ulonglong2*)(hb + (kg * 8 + r) * 8);
                const ulonglong2 p0 = ph[0], p1 = ph[1];
                a0 = fma2(ws, p0.x, a0);
                a1 = fma2(ws, p0.y, a1);
                a2 = fma2(ws, p1.x, a2);
                a3 = fma2(ws, p1.y, a3);
            }
            a0 = add2(a0, __shfl_down_sync(0xffffffffu, a0, 16));
            a1 = add2(a1, __shfl_down_sync(0xffffffffu, a1, 16));
            a2 = add2(a2, __shfl_down_sync(0xffffffffu, a2, 16));
            a3 = add2(a3, __shfl_down_sync(0xffffffffu, a3, 16));
            if ((tid & 31) < 16) {
                ulonglong2* q = (ulonglong2*)(red2 + (wid * 16 + j2) * 8);
                q[0] = make_ulonglong2(a0, a1);    // floats {b0,b1,b2,b3}
                q[1] = make_ulonglong2(a2, a3);    // floats {b4,b5,b6,b7}
            }
        }
        // ---- layer-1 partials (4 k) + shfl-combine (4 kg) -> red1 ----
        {
            ull q0 = 0, q1 = 0, q2 = 0, q3 = 0;
#pragma unroll
            for (int r = 0; r < 4; ++r) {
                const ull ws = splat2(w1_r[r]);
                const ulonglong2* ph = (const ulonglong2*)(hb + (kg1 * 4 + r) * 8);
                const ulonglong2 p0 = ph[0], p1 = ph[1];
                q0 = fma2(ws, p0.x, q0);
                q1 = fma2(ws, p0.y, q1);
                q2 = fma2(ws, p1.x, q2);
                q3 = fma2(ws, p1.y, q3);
            }
            q0 = add2(q0, __shfl_down_sync(0xffffffffu, q0, 8));
            q1 = add2(q1, __shfl_down_sync(0xffffffffu, q1, 8));
            q2 = add2(q2, __shfl_down_sync(0xffffffffu, q2, 8));
            q3 = add2(q3, __shfl_down_sync(0xffffffffu, q3, 8));
            q0 = add2(q0, __shfl_down_sync(0xffffffffu, q0, 16));
            q1 = add2(q1, __shfl_down_sync(0xffffffffu, q1, 16));
            q2 = add2(q2, __shfl_down_sync(0xffffffffu, q2, 16));
            q3 = add2(q3, __shfl_down_sync(0xffffffffu, q3, 16));
            if ((tid & 31) < 8) {
                ulonglong2* q = (ulonglong2*)(red1 + (wid * 8 + j1) * 8);
                q[0] = make_ulonglong2(q0, q1);
                q[1] = make_ulonglong2(q2, q3);
            }
        }
        __syncthreads();

        // ---- finishers (disjoint threads) and stagers ----
        if (tid < 128) {
            // layer-2 finish: b = tid&7, jf = tid>>3 in [0,16)
            const int b = tid & 7, jf = tid >> 3;
            float s = b2_s[jf];
            const int off = jf * 8 + b;
#pragma unroll
            for (int w = 0; w < 16; ++w) s += red2[w * 128 + off];
            s = fmaxf(s, 0.f);
            if (t == 511) g_h2[(B0 + 8 * g + b) * 512 + c2 + jf] = s;
            else          __stcg(&g_h2T[cl][g][(t + 1) & 1][c2 + jf][b], s);
        } else if (tid < 192 && t < 511) {
            // layer-1 finish: b = ii&7, jj = ii>>3 in [0,8)
            const int ii = tid - 128, b = ii & 7, jj = ii >> 3;
            float s = xnext;
            const int off = jj * 8 + b;
#pragma unroll
            for (int w = 0; w < 16; ++w) s += red1[w * 64 + off];
            __stcg(&g_h1T[cl][g][(t + 1) & 1][c1 + jj][b], fmaxf(s, 0.f));
        } else if (tid >= 256 && do_stage) {
            // stage prefetched h(g^1, tn) into hd[g^1] verbatim (no splat)
            const int s = tid - 256;
            float* d = hd + (size_t)(g ^ 1) * 6144;
            *(float4*)(d + s * 8)             = pl0;
            *(float4*)(d + s * 8 + 4)         = ph0;
            *(float4*)(d + (s + 256) * 8)     = pl1;
            *(float4*)(d + (s + 256) * 8 + 4) = ph1;
            *(float4*)(d + (s + 512) * 8)     = pl2;
            *(float4*)(d + (s + 512) * 8 + 4) = ph2;
        }
        __syncthreads();

        // ---- publish completion of h(g, t+1) ----
        if (t < 511 && tid == 0) {
            fence_gpu_();
            flag_add1(&g_flag[cl][g][0]);
        }
    }
}

// =====================================================================
// Kernel 3: MLP head (256 threads, k-split partials)
// =====================================================================
__global__ void __launch_bounds__(256, 1)
head_kernel(const float* __restrict__ Wd1, const float* __restrict__ bd1,
            const float* __restrict__ Wd2, const float* __restrict__ bd2,
            const float* __restrict__ Wc,  const float* __restrict__ bc,
            float* __restrict__ out)
{
    __shared__ float h_s[512], p1[2][128], d1_s[128], p2[2][64], d2_s[64];
    const int b = blockIdx.x, tid = threadIdx.x;

    for (int k = tid; k < 512; k += 256) h_s[k] = g_h2[b * 512 + k];
    __syncthreads();

    {
        const int col = tid & 127, half = tid >> 7;
        float a0 = 0.f, a1 = 0.f;
        const float* wp = Wd1 + (size_t)(half * 256) * 128 + col;
        const float* hp = h_s + half * 256;
#pragma unroll 4
        for (int k = 0; k < 256; k += 2) {
            a0 = fmaf(hp[k],     __ldg(wp + (size_t)k * 128), a0);
            a1 = fmaf(hp[k + 1], __ldg(wp + (size_t)(k + 1) * 128), a1);
        }
        p1[half][col] = a0 + a1;
    }
    __syncthreads();
    if (tid < 128) d1_s[tid] = fmaxf(p1[0][tid] + p1[1][tid] + __ldg(bd1 + tid), 0.f);
    __syncthreads();

    if (tid < 128) {
        const int col = tid & 63, half = tid >> 6;
        float a0 = 0.f, a1 = 0.f;
        const float* wp = Wd2 + (size_t)(half * 64) * 64 + col;
        const float* hp = d1_s + half * 64;
#pragma unroll 4
        for (int k = 0; k < 64; k += 2) {
            a0 = fmaf(hp[k],     __ldg(wp + (size_t)k * 64), a0);
            a1 = fmaf(hp[k + 1], __ldg(wp + (size_t)(k + 1) * 64), a1);
        }
        p2[half][col] = a0 + a1;
    }
    __syncthreads();
    if (tid < 64) d2_s[tid] = fmaxf(p2[0][tid] + p2[1][tid] + __ldg(bd2 + tid), 0.f);
    __syncthreads();

    if (tid < 32) {
        float p = d2_s[tid] * __ldg(Wc + tid) + d2_s[tid + 32] * __ldg(Wc + tid + 32);
#pragma unroll
        for (int o = 16; o; o >>= 1) p += __shfl_down_sync(0xffffffffu, p, o);
        if (tid == 0) out[b] = 1.f / (1.f + expf(-(p + __ldg(bc))));
    }
}

// =====================================================================
extern "C" void kernel_launch(void* const* d_in, const int* in_sizes, int n_in,
                              void* d_out, int out_size)
{
    const int*   tokens = (const int*)  d_in[0];
    const float* emb    = (const float*)d_in[1];
    const float* W1x    = (const float*)d_in[2];
    const float* W1h    = (const float*)d_in[3];
    const float* b1     = (const float*)d_in[4];
    const float* W2x    = (const float*)d_in[5];
    const float* W2h    = (const float*)d_in[6];
    const float* b2     = (const float*)d_in[7];
    const float* Wd1    = (const float*)d_in[8];
    const float* bd1    = (const float*)d_in[9];
    const float* Wd2    = (const float*)d_in[10];
    const float* bd2    = (const float*)d_in[11];
    const float* Wc     = (const float*)d_in[12];
    const float* bc     = (const float*)d_in[13];
    float* out = (float*)d_out;
    (void)in_sizes; (void)n_in; (void)out_size;

    cudaFuncSetAttribute(rnn_kernel,
                         cudaFuncAttributeMaxDynamicSharedMemorySize,
                         RNN_SMEM_BYTES);

    embproj_kernel<<<1024, 256>>>(tokens, emb, W1x, b1);
    nop_kernel<<<1, 32>>>();
    nop_kernel2<<<1, 32>>>();   // global launch idx 3 == rnn_kernel (ncu slot)
    rnn_kernel<<<128, 512, RNN_SMEM_BYTES>>>(W1h, W2x, W2h, b2);
    head_kernel<<<64, 256>>>(Wd1, bd1, Wd2, bd2, Wc, bc, out);
}

// round 17
// speedup vs baseline: 1.1738x; 1.1738x over previous
#include <cuda_runtime.h>
#include <math.h>

// Problem: B=64, T=512, V=50000, E=300, H1=256, H2=512, D1=128, D2=64, C=1
// Inputs: tokens, emb, W1x, W1h, b1, W2x, W2h, b2, Wd1, bd1, Wd2, bd2, Wc, bc

typedef unsigned long long ull;

// ---------------- packed f32x2 helpers ----------------
__device__ __forceinline__ ull pack2(float lo, float hi) {
    ull r; asm("mov.b64 %0,{%1,%2};" : "=l"(r) : "f"(lo), "f"(hi)); return r;
}
__device__ __forceinline__ ull splat2(float v) { return pack2(v, v); }
__device__ __forceinline__ float2 unpack2(ull v) {
    float2 r; asm("mov.b64 {%0,%1},%2;" : "=f"(r.x), "=f"(r.y) : "l"(v)); return r;
}
__device__ __forceinline__ ull fma2(ull a, ull b, ull c) {
    ull d; asm("fma.rn.f32x2 %0,%1,%2,%3;" : "=l"(d) : "l"(a), "l"(b), "l"(c)); return d;
}
__device__ __forceinline__ ull add2(ull a, ull b) {
    ull d; asm("add.rn.f32x2 %0,%1,%2;" : "=l"(d) : "l"(a), "l"(b)); return d;
}
// ---------------- L2 flag sync (no cluster, no sleep) ----------------
__device__ __forceinline__ void fence_gpu_() {
    asm volatile("fence.acq_rel.gpu;" ::: "memory");
}
__device__ __forceinline__ void flag_add1(unsigned* p) {
    asm volatile("red.relaxed.gpu.global.add.u32 [%0], 1;" :: "l"(p) : "memory");
}
__device__ __forceinline__ unsigned flag_ld(const unsigned* p) {
    unsigned v;
    asm volatile("ld.acquire.gpu.global.u32 %0, [%1];" : "=r"(v) : "l"(p) : "memory");
    return v;
}

// ---------------- static device scratch ----------------
__device__ float g_xw1[(size_t)64 * 512 * 256];       // xw1[b][t][j]
__device__ float g_h1T[8][2][2][256][4];              // [cl][g][buf][k][b]
__device__ float g_h2T[8][2][2][512][4];
__device__ float g_h2[64 * 512];                      // final h2(511) for the head
__device__ __align__(128) unsigned g_flag[8][2][32];  // [cl][g][line]

// =====================================================================
// Kernel 1: xw1[b,t,:] = emb[tokens[b,t]] @ W1x + b1  (+ flag reset)
// v2: unroll 6 + 2-stage weight prefetch (MLP ~8-12, was ~4 -> latency
// bound at 210us with fma pipe 33.7%; target the ~75us FMA floor).
// =====================================================================
__global__ void __launch_bounds__(256, 2)
embproj_kernel(const int* __restrict__ tokens, const float* __restrict__ emb,
               const float* __restrict__ W1x, const float* __restrict__ b1)
{
    __shared__ int    t_sm[32];
    __shared__ float4 a_sm[300 * 9];

    const int tid  = threadIdx.x;
    const int base = blockIdx.x * 32;

    // reset group sync counters for this launch (graph replays included)
    if (blockIdx.x == 0 && tid < 16) g_flag[tid >> 1][tid & 1][0] = 0u;

    if (tid < 32) t_sm[tid] = tokens[base + tid];
    __syncthreads();

    {
        const int m4 = tid >> 6;
        const int e0 = tid & 63;
        for (int mm = m4; mm < 8; mm += 4) {
            const int i0 = mm * 4;
            const size_t r0 = (size_t)t_sm[i0 + 0] * 300;
            const size_t r1 = (size_t)t_sm[i0 + 1] * 300;
            const size_t r2 = (size_t)t_sm[i0 + 2] * 300;
            const size_t r3 = (size_t)t_sm[i0 + 3] * 300;
            for (int e = e0; e < 300; e += 64) {
                float4 v;
                v.x = __ldg(emb + r0 + e);
                v.y = __ldg(emb + r1 + e);
                v.z = __ldg(emb + r2 + e);
                v.w = __ldg(emb + r3 + e);
                a_sm[e * 9 + mm] = v;
            }
        }
    }
    __syncthreads();

    const int j = tid;
    ull acc[16];
#pragma unroll
    for (int m = 0; m < 16; ++m) acc[m] = 0ull;

    const float* wp = W1x + j;
    float wcur = __ldg(wp);              // prefetch pipeline: w[e]
#pragma unroll 6
    for (int e = 0; e < 300; ++e) {
        float wnext = 0.f;
        if (e + 1 < 300) wnext = __ldg(wp + (size_t)(e + 1) * 256);
        const ull ws = splat2(wcur);
        const ulonglong2* ap = (const ulonglong2*)(a_sm + e * 9);
#pragma unroll
        for (int m2 = 0; m2 < 8; ++m2) {
            ulonglong2 s = ap[m2];
            acc[2 * m2]     = fma2(ws, s.x, acc[2 * m2]);
            acc[2 * m2 + 1] = fma2(ws, s.y, acc[2 * m2 + 1]);
        }
        wcur = wnext;
    }

    const float bj = __ldg(b1 + j);
#pragma unroll
    for (int m = 0; m < 16; ++m) {
        float2 v = unpack2(acc[m]);
        const size_t row = (size_t)(base + 2 * m);
        g_xw1[row * 256 + j]       = v.x + bj;
        g_xw1[(row + 1) * 256 + j] = v.y + bj;
    }
}

// =====================================================================
// nop kernels: keep ncu capture landing on rnn_kernel (launch idx 3)
// =====================================================================
__global__ void nop_kernel() {}
__global__ void nop_kernel2() {}

// =====================================================================
// Kernel 2: fused 2-layer recurrence (v12 = R15 champion, unchanged).
// 128 plain CTAs in 8 groups of 16; group owns 8 batches as 2 pipelined
// sub-groups of 4 (g = n&1, t = n>>1, 1024 iterations). CTA r owns
// layer-2 cols [32r,+32), layer-1 cols [16r,+16): W2h slice = 64 KB.
// W2x (8 ull) + W1h (4 ull) in regs; shfl pre-reduction; L2 flag-spin
// sync with mid-compute poll+prefetch on stager threads.
// =====================================================================
#define RNN_SMEM_BYTES 127104

__global__ void __launch_bounds__(512, 1)
rnn_kernel(const float* __restrict__ W1h, const float* __restrict__ W2x,
           const float* __restrict__ W2h, const float* __restrict__ b2)
{
    extern __shared__ float smem[];
    float*  w2h_s = smem;                          // [512][32]   64 KB
    float4* hdAB  = (float4*)(smem + 16384);       // [2][768] {b0,b0,b1,b1}
    float4* hdCD  = hdAB + 1536;                   // [2][768] {b2,b2,b3,b3}
    float*  red2  = (float*)(hdCD + 1536);         // [16][16][8]  8 KB
    float*  red1  = red2 + 2048;                   // [16][8][8]   4 KB
    float*  b2_s  = red1 + 1024;                   // [32]

    const int tid  = threadIdx.x;
    const int rank = blockIdx.x & 15;
    const int cl   = blockIdx.x >> 4;              // 8 groups
    const int B0   = cl * 8;
    const int c1 = rank * 16, c2 = rank * 32;
    const int jp  = tid & 15, kg  = tid >> 4;      // layer-2: 32 kg x 16 colpairs
    const int jq  = tid & 7,  kg1 = tid >> 3;      // layer-1: 64 kg x 8 colpairs
    const int wid = tid >> 5;

    // ---- W2h slice -> SMEM ----
    for (int idx = tid; idx < 512 * 32; idx += 512) {
        const int k = idx >> 5, j = idx & 31;
        w2h_s[idx] = W2h[(size_t)k * 512 + c2 + j];
    }
    // ---- W2x slice -> registers (k in [8kg, 8kg+8)) ----
    ull w2x_r[8];
#pragma unroll
    for (int r = 0; r < 8; ++r)
        w2x_r[r] = *(const ull*)(W2x + (size_t)(kg * 8 + r) * 512 + c2 + 2 * jp);
    // ---- W1h slice -> registers (k in [4kg1, 4kg1+4)) ----
    ull w1_r[4];
#pragma unroll
    for (int r = 0; r < 4; ++r)
        w1_r[r] = *(const ull*)(W1h + (size_t)(kg1 * 4 + r) * 256 + c1 + 2 * jq);
    if (tid < 32) b2_s[tid] = b2[c2 + tid];

    // ---- init hd[0], hd[1]: h1(g,0) = relu(xw1); h2(g,-1) = 0 ----
    for (int idx = tid; idx < 1536; idx += 512) {
        const int g = idx >= 768, k = idx - g * 768;
        float v0 = 0.f, v1 = 0.f, v2 = 0.f, v3 = 0.f;
        if (k < 256) {
            v0 = fmaxf(g_xw1[(size_t)((B0 + 4 * g)     * 512) * 256 + k], 0.f);
            v1 = fmaxf(g_xw1[(size_t)((B0 + 4 * g + 1) * 512) * 256 + k], 0.f);
            v2 = fmaxf(g_xw1[(size_t)((B0 + 4 * g + 2) * 512) * 256 + k], 0.f);
            v3 = fmaxf(g_xw1[(size_t)((B0 + 4 * g + 3) * 512) * 256 + k], 0.f);
        }
        hdAB[g * 768 + k] = make_float4(v0, v0, v1, v1);
        hdCD[g * 768 + k] = make_float4(v2, v2, v3, v3);
    }
    __syncthreads();
    // flags start at 0 (reset by embproj); h(g,0) lives only in local SMEM.

    for (int n = 0; n < 1024; ++n) {
        const int g = n & 1, t = n >> 1;
        const int tn = (n + 1) >> 1;               // timestep of NEXT iteration
        const bool do_stage = (n >= 1) && (n < 1023);

        // xnext for layer-1 finish (threads 128..191)
        float xnext = 0.f;
        if (tid >= 128 && tid < 192 && t < 511) {
            const int ii = tid - 128, b = ii & 3, jj = ii >> 2;
            xnext = __ldcg(&g_xw1[((size_t)((B0 + 4 * g + b) * 512 + t + 1)) * 256 + c1 + jj]);
        }

        ull a0 = 0, a1 = 0, a2 = 0, a3 = 0;

        // ---- compute part 1: W2h.h2 (16 k per thread) ----
        {
            const ulonglong2* pB = (const ulonglong2*)(hdAB + g * 768 + 256) + kg * 16;
            const ulonglong2* pD = (const ulonglong2*)(hdCD + g * 768 + 256) + kg * 16;
            const float* wp = w2h_s + (kg * 16) * 32 + 2 * jp;
#pragma unroll
            for (int r = 0; r < 16; ++r) {
                const ull w = *(const ull*)(wp + r * 32);
                const ulonglong2 sB = pB[r], sD = pD[r];
                a0 = fma2(w, sB.x, a0);
                a1 = fma2(w, sB.y, a1);
                a2 = fma2(w, sD.x, a2);
                a3 = fma2(w, sD.y, a3);
            }
        }

        // ---- mid-compute: stagers poll (fast path) + prefetch next h ----
        float4 pre0, pre1, pre2;
        if (do_stage && tid >= 256) {
            const unsigned target = 16u * (unsigned)tn;
            const unsigned* fp = &g_flag[cl][g ^ 1][0];
            while (flag_ld(fp) < target) { }
            const int st = tid - 256;              // 0..255
            const int nb = tn & 1;
            pre0 = __ldcg((const float4*)&g_h1T[cl][g ^ 1][nb][st][0]);
            pre1 = __ldcg((const float4*)&g_h2T[cl][g ^ 1][nb][st][0]);
            pre2 = __ldcg((const float4*)&g_h2T[cl][g ^ 1][nb][st + 256][0]);
        }

        // ---- compute part 2: W2x.h1 (8 k) + shfl-combine -> red2 ----
        {
            const ulonglong2* pA = (const ulonglong2*)(hdAB + g * 768) + kg * 8;
            const ulonglong2* pC = (const ulonglong2*)(hdCD + g * 768) + kg * 8;
#pragma unroll
            for (int r = 0; r < 8; ++r) {
                const ulonglong2 sA = pA[r], sC = pC[r];
                a0 = fma2(w2x_r[r], sA.x, a0);
                a1 = fma2(w2x_r[r], sA.y, a1);
                a2 = fma2(w2x_r[r], sC.x, a2);
                a3 = fma2(w2x_r[r], sC.y, a3);
            }
            // combine kg pairs (lanes l, l+16 have kg, kg+1; same jp)
            a0 = add2(a0, __shfl_down_sync(0xffffffffu, a0, 16));
            a1 = add2(a1, __shfl_down_sync(0xffffffffu, a1, 16));
            a2 = add2(a2, __shfl_down_sync(0xffffffffu, a2, 16));
            a3 = add2(a3, __shfl_down_sync(0xffffffffu, a3, 16));
            if ((tid & 31) < 16) {
                const float2 v0 = unpack2(a0), v1 = unpack2(a1);
                const float2 v2 = unpack2(a2), v3 = unpack2(a3);
                float4* q = (float4*)(red2 + ((kg >> 1) * 16 + jp) * 8);
                q[0] = make_float4(v0.x, v0.y, v1.x, v1.y);
                q[1] = make_float4(v2.x, v2.y, v3.x, v3.y);
            }
        }
        // ---- layer-1 partials (4 k) + shfl-combine (4 kg) -> red1 ----
        {
            ull q0 = 0, q1 = 0, q2 = 0, q3 = 0;
            const ulonglong2* pA = (const ulonglong2*)(hdAB + g * 768) + kg1 * 4;
            const ulonglong2* pC = (const ulonglong2*)(hdCD + g * 768) + kg1 * 4;
#pragma unroll
            for (int r = 0; r < 4; ++r) {
                const ulonglong2 sA = pA[r], sC = pC[r];
                q0 = fma2(w1_r[r], sA.x, q0);
                q1 = fma2(w1_r[r], sA.y, q1);
                q2 = fma2(w1_r[r], sC.x, q2);
                q3 = fma2(w1_r[r], sC.y, q3);
            }
            q0 = add2(q0, __shfl_down_sync(0xffffffffu, q0, 16));
            q1 = add2(q1, __shfl_down_sync(0xffffffffu, q1, 16));
            q2 = add2(q2, __shfl_down_sync(0xffffffffu, q2, 16));
            q3 = add2(q3, __shfl_down_sync(0xffffffffu, q3, 16));
            q0 = add2(q0, __shfl_down_sync(0xffffffffu, q0, 8));
            q1 = add2(q1, __shfl_down_sync(0xffffffffu, q1, 8));
            q2 = add2(q2, __shfl_down_sync(0xffffffffu, q2, 8));
            q3 = add2(q3, __shfl_down_sync(0xffffffffu, q3, 8));
            if ((tid & 31) < 8) {
                const float2 u0 = unpack2(q0), u1 = unpack2(q1);
                const float2 u2 = unpack2(q2), u3 = unpack2(q3);
                float4* q = (float4*)(red1 + (wid * 8 + jq) * 8);
                q[0] = make_float4(u0.x, u0.y, u1.x, u1.y);
                q[1] = make_float4(u2.x, u2.y, u3.x, u3.y);
            }
        }
        __syncthreads();

        // ---- finishers (disjoint) and stagers ----
        if (tid < 128) {
            // layer-2 finish: (b = tid&3, jf = tid>>2 in [0,32))
            const int b = tid & 3, jf = tid >> 2;
            float s = b2_s[jf];
            const int off = (jf >> 1) * 8 + b * 2 + (jf & 1);
#pragma unroll
            for (int g2 = 0; g2 < 16; ++g2) s += red2[g2 * 128 + off];
            s = fmaxf(s, 0.f);
            if (t == 511) g_h2[(B0 + 4 * g + b) * 512 + c2 + jf] = s;
            else          __stcg(&g_h2T[cl][g][(t + 1) & 1][c2 + jf][b], s);
        } else if (tid < 192 && t < 511) {
            // layer-1 finish: (b = ii&3, jj = ii>>2 in [0,16))
            const int ii = tid - 128, b = ii & 3, jj = ii >> 2;
            float s = xnext;
            const int off = (jj >> 1) * 8 + b * 2 + (jj & 1);
#pragma unroll
            for (int g2 = 0; g2 < 16; ++g2) s += red1[g2 * 64 + off];
            __stcg(&g_h1T[cl][g][(t + 1) & 1][c1 + jj][b], fmaxf(s, 0.f));
        } else if (tid >= 256 && do_stage) {
            // stage prefetched h(g^1, tn) into hd[g^1], splatted
            const int st = tid - 256;
            float4* dA = hdAB + (g ^ 1) * 768;
            float4* dC = hdCD + (g ^ 1) * 768;
            dA[st]       = make_float4(pre0.x, pre0.x, pre0.y, pre0.y);
            dC[st]       = make_float4(pre0.z, pre0.z, pre0.w, pre0.w);
            dA[st + 256] = make_float4(pre1.x, pre1.x, pre1.y, pre1.y);
            dC[st + 256] = make_float4(pre1.z, pre1.z, pre1.w, pre1.w);
            dA[st + 512] = make_float4(pre2.x, pre2.x, pre2.y, pre2.y);
            dC[st + 512] = make_float4(pre2.z, pre2.z, pre2.w, pre2.w);
        }
        __syncthreads();

        // ---- publish completion of h(g, t+1) ----
        if (t < 511 && tid == 0) {
            fence_gpu_();
            flag_add1(&g_flag[cl][g][0]);
        }
    }
}

// =====================================================================
// Kernel 3: MLP head (256 threads, k-split partials)
// =====================================================================
__global__ void __launch_bounds__(256, 1)
head_kernel(const float* __restrict__ Wd1, const float* __restrict__ bd1,
            const float* __restrict__ Wd2, const float* __restrict__ bd2,
            const float* __restrict__ Wc,  const float* __restrict__ bc,
            float* __restrict__ out)
{
    __shared__ float h_s[512], p1[2][128], d1_s[128], p2[2][64], d2_s[64];
    const int b = blockIdx.x, tid = threadIdx.x;

    for (int k = tid; k < 512; k += 256) h_s[k] = g_h2[b * 512 + k];
    __syncthreads();

    {
        const int col = tid & 127, half = tid >> 7;
        float a0 = 0.f, a1 = 0.f;
        const float* wp = Wd1 + (size_t)(half * 256) * 128 + col;
        const float* hp = h_s + half * 256;
#pragma unroll 4
        for (int k = 0; k < 256; k += 2) {
            a0 = fmaf(hp[k],     __ldg(wp + (size_t)k * 128), a0);
            a1 = fmaf(hp[k + 1], __ldg(wp + (size_t)(k + 1) * 128), a1);
        }
        p1[half][col] = a0 + a1;
    }
    __syncthreads();
    if (tid < 128) d1_s[tid] = fmaxf(p1[0][tid] + p1[1][tid] + __ldg(bd1 + tid), 0.f);
    __syncthreads();

    if (tid < 128) {
        const int col = tid & 63, half = tid >> 6;
        float a0 = 0.f, a1 = 0.f;
        const float* wp = Wd2 + (size_t)(half * 64) * 64 + col;
        const float* hp = d1_s + half * 64;
#pragma unroll 4
        for (int k = 0; k < 64; k += 2) {
            a0 = fmaf(hp[k],     __ldg(wp + (size_t)k * 64), a0);
            a1 = fmaf(hp[k + 1], __ldg(wp + (size_t)(k + 1) * 64), a1);
        }
        p2[half][col] = a0 + a1;
    }
    __syncthreads();
    if (tid < 64) d2_s[tid] = fmaxf(p2[0][tid] + p2[1][tid] + __ldg(bd2 + tid), 0.f);
    __syncthreads();

    if (tid < 32) {
        float p = d2_s[tid] * __ldg(Wc + tid) + d2_s[tid + 32] * __ldg(Wc + tid + 32);
#pragma unroll
        for (int o = 16; o; o >>= 1) p += __shfl_down_sync(0xffffffffu, p, o);
        if (tid == 0) out[b] = 1.f / (1.f + expf(-(p + __ldg(bc))));
    }
}

// =====================================================================
extern "C" void kernel_launch(void* const* d_in, const int* in_sizes, int n_in,
                              void* d_out, int out_size)
{
    const int*   tokens = (const int*)  d_in[0];
    const float* emb    = (const float*)d_in[1];
    const float* W1x    = (const float*)d_in[2];
    const float* W1h    = (const float*)d_in[3];
    const float* b1     = (const float*)d_in[4];
    const float* W2x    = (const float*)d_in[5];
    const float* W2h    = (const float*)d_in[6];
    const float* b2     = (const float*)d_in[7];
    const float* Wd1    = (const float*)d_in[8];
    const float* bd1    = (const float*)d_in[9];
    const float* Wd2    = (const float*)d_in[10];
    const float* bd2    = (const float*)d_in[11];
    const float* Wc     = (const float*)d_in[12];
    const float* bc     = (const float*)d_in[13];
    float* out = (float*)d_out;
    (void)in_sizes; (void)n_in; (void)out_size;

    cudaFuncSetAttribute(rnn_kernel,
                         cudaFuncAttributeMaxDynamicSharedMemorySize,
                         RNN_SMEM_BYTES);

    embproj_kernel<<<1024, 256>>>(tokens, emb, W1x, b1);
    nop_kernel<<<1, 32>>>();
    nop_kernel2<<<1, 32>>>();   // global launch idx 3 == rnn_kernel (ncu slot)
    rnn_kernel<<<128, 512, RNN_SMEM_BYTES>>>(W1h, W2x, W2h, b2);
    head_kernel<<<64, 256>>>(Wd1, bd1, Wd2, bd2, Wc, bc, out);
}